// round 1
// baseline (speedup 1.0000x reference)
#include <cuda_runtime.h>
#include <math.h>

typedef unsigned long long u64;

#define BT 4096     // B*T rows
#define TT 512
#define BB 8
#define EE 512
#define HH 1024
#define H4 4096
#define CC 32000
#define WS_STRIDE 1028   // padded row stride (floats) for conflict-free smem

// ---------------- scratch (device globals; no allocation allowed) ----------
__device__ float g_X0[(size_t)BT * EE];        // embedded input   8 MB
__device__ float g_XG[(size_t)BT * H4];        // gate pre-acts   64 MB (reused)
__device__ float g_H0[(size_t)BT * HH];        // layer0 hidden   16 MB
__device__ float g_H1[(size_t)BT * HH];        // layer1 hidden   16 MB
__device__ float g_h[2][BB * HH];              // h double buffer
__device__ unsigned g_barcnt;                  // grid barrier counter

// ---------------- f32x2 helpers (Blackwell packed fp32: 2x FMA rate) -------
__device__ __forceinline__ void fma2(u64 &d, u64 a, u64 b) {
    asm("fma.rn.f32x2 %0, %1, %2, %0;" : "+l"(d) : "l"(a), "l"(b));
}
__device__ __forceinline__ float hsum2(u64 v) {
    float lo, hi;
    asm("mov.b64 {%0,%1}, %2;" : "=f"(lo), "=f"(hi) : "l"(v));
    return lo + hi;
}

// ---------------- embedding gather -----------------------------------------
__global__ void embed_kernel(const int* __restrict__ x, const float* __restrict__ emb) {
    int row = blockIdx.x;                 // 0..4095 = b*T+t
    int id = x[row];
    const float4* s = (const float4*)(emb + (size_t)id * EE);
    float4* d = (float4*)(g_X0 + (size_t)row * EE);
    int i = threadIdx.x;
    if (i < EE / 4) d[i] = s[i];
}

// ---------------- GEMM: C[M,N] = A[M,K] @ W[N,K]^T + b1[n] (+ b2[n]) -------
// BM=128, BN=128, BK=16, 512 threads, thread tile 8x4, k-pair f32x2 packing.
// All dims are multiples of 128/16 for this problem (M=4096, N=4096|32000).
__global__ void __launch_bounds__(512, 1) gemm_nt_kernel(
    const float* __restrict__ A, const float* __restrict__ W,
    const float* __restrict__ b1, const float* __restrict__ b2,
    float* __restrict__ Cmat, int M, int N, int K)
{
    __shared__ float As[128][18];   // pad 18 -> conflict-reduced, 8B aligned rows
    __shared__ float Ws[128][18];
    const int t  = threadIdx.x;
    const int tx = t & 31;          // n direction: cols tx, tx+32, tx+64, tx+96
    const int ty = t >> 5;          // m direction: rows ty*8 .. ty*8+7
    const int m0 = blockIdx.y << 7;
    const int n0 = blockIdx.x << 7;

    u64 acc[8][4];
#pragma unroll
    for (int i = 0; i < 8; i++)
#pragma unroll
        for (int j = 0; j < 4; j++) acc[i][j] = 0ull;

    const int lrow = t >> 2;
    const int lc4  = (t & 3) << 2;
    const float* Ap = A + (size_t)(m0 + lrow) * K + lc4;
    const float* Wp = W + (size_t)(n0 + lrow) * K + lc4;

    float4 av = __ldg((const float4*)Ap);
    float4 wv = __ldg((const float4*)Wp);

    for (int k0 = 0; k0 < K; k0 += 16) {
        As[lrow][lc4 + 0] = av.x; As[lrow][lc4 + 1] = av.y;
        As[lrow][lc4 + 2] = av.z; As[lrow][lc4 + 3] = av.w;
        Ws[lrow][lc4 + 0] = wv.x; Ws[lrow][lc4 + 1] = wv.y;
        Ws[lrow][lc4 + 2] = wv.z; Ws[lrow][lc4 + 3] = wv.w;
        __syncthreads();

        if (k0 + 16 < K) {   // prefetch next tile while computing
            av = __ldg((const float4*)(Ap + k0 + 16));
            wv = __ldg((const float4*)(Wp + k0 + 16));
        }

#pragma unroll
        for (int kk = 0; kk < 16; kk += 2) {
            u64 a2[8], b2r[4];
#pragma unroll
            for (int i = 0; i < 8; i++)
                a2[i] = *(const u64*)&As[ty * 8 + i][kk];
#pragma unroll
            for (int j = 0; j < 4; j++)
                b2r[j] = *(const u64*)&Ws[tx + (j << 5)][kk];
#pragma unroll
            for (int i = 0; i < 8; i++)
#pragma unroll
                for (int j = 0; j < 4; j++) fma2(acc[i][j], a2[i], b2r[j]);
        }
        __syncthreads();
    }

#pragma unroll
    for (int j = 0; j < 4; j++) {
        int n = n0 + tx + (j << 5);
        float bias = __ldg(&b1[n]) + (b2 ? __ldg(&b2[n]) : 0.f);
#pragma unroll
        for (int i = 0; i < 8; i++) {
            Cmat[(size_t)(m0 + ty * 8 + i) * N + n] = hsum2(acc[i][j]) + bias;
        }
    }
}

// ---------------- LSTM recurrence: persistent kernel -----------------------
// 128 blocks x 256 threads (one block per SM, all co-resident -> custom grid
// barrier is safe). Block `blk` owns hidden units j = blk*8..blk*8+7, i.e.
// the 32 Whh rows {G*1024 + blk*8 + u}, held in smem for all 512 steps.
// Thread (r = tid/8, b = tid%8) computes one dot product of length 1024 per
// step using f32x2 FMAs. Gate combine + cell update done by threads 0..63.
__device__ __forceinline__ float sigmoidf_(float x) { return 1.f / (1.f + expf(-x)); }

__global__ void __launch_bounds__(256, 1) lstm_kernel(
    const float* __restrict__ Whh,   // [4096, 1024]
    const float* __restrict__ XG,    // [(b*T+t), 4096] input pre-acts + biases
    float* __restrict__ Hout)        // [(b*T+t), 1024]
{
    extern __shared__ float smem[];
    float* ws = smem;                        // [32][WS_STRIDE]
    float* hs = smem + 32 * WS_STRIDE;       // [8][WS_STRIDE]
    __shared__ float gate_s[32][8];
    __shared__ float c_s[64];                // cell state [unit][batch]

    const int tid = threadIdx.x;
    const int blk = blockIdx.x;

    // Load this block's 32 Whh rows into smem (once).
    for (int idx = tid; idx < 32 * 256; idx += 256) {
        int r  = idx >> 8;
        int c4 = (idx & 255) << 2;
        int gr = ((r >> 3) << 10) + (blk << 3) + (r & 7);
        float4 v = __ldg((const float4*)(Whh + (size_t)gr * HH + c4));
        *(float4*)&ws[r * WS_STRIDE + c4] = v;
    }
    if (tid < 64) c_s[tid] = 0.f;

    const int r = tid >> 3, b = tid & 7;
    const int G = r >> 3, u = r & 7;
    const int grow = (G << 10) + (blk << 3) + u;
    const float* wr = ws + r * WS_STRIDE;
    const float* hr = hs + b * WS_STRIDE;

    unsigned target = 0;
    for (int t = 0; t < TT; t++) {
        const int cur = t & 1;
        // Pull h (written by other SMs last step) into smem; .cg bypasses
        // stale L1 lines from two steps ago.
        for (int idx = tid; idx < 2048; idx += 256) {
            int bb = idx >> 8;
            int c4 = (idx & 255) << 2;
            float4 v = __ldcg((const float4*)&g_h[cur][bb * HH + c4]);
            *(float4*)&hs[bb * WS_STRIDE + c4] = v;
        }
        __syncthreads();

        u64 acc0 = 0ull, acc1 = 0ull;
#pragma unroll 4
        for (int k = 0; k < HH; k += 8) {
            ulonglong2 w0 = *(const ulonglong2*)(wr + k);
            ulonglong2 h0 = *(const ulonglong2*)(hr + k);
            ulonglong2 w1 = *(const ulonglong2*)(wr + k + 4);
            ulonglong2 h1 = *(const ulonglong2*)(hr + k + 4);
            fma2(acc0, w0.x, h0.x); fma2(acc1, w0.y, h0.y);
            fma2(acc0, w1.x, h1.x); fma2(acc1, w1.y, h1.y);
        }
        float s = hsum2(acc0) + hsum2(acc1);
        float gin = __ldg(&XG[(size_t)((b << 9) + t) * H4 + grow]);
        gate_s[r][b] = gin + s;
        __syncthreads();

        if (tid < 64) {
            int uu = tid >> 3, bb2 = tid & 7;
            float gi = sigmoidf_(gate_s[uu][bb2]);
            float gf = sigmoidf_(gate_s[8 + uu][bb2]);
            float gg = tanhf(gate_s[16 + uu][bb2]);
            float go = sigmoidf_(gate_s[24 + uu][bb2]);
            float c = gf * c_s[tid] + gi * gg;
            c_s[tid] = c;
            float h = go * tanhf(c);
            int j = (blk << 3) + uu;
            g_h[cur ^ 1][bb2 * HH + j] = h;
            Hout[(size_t)((bb2 << 9) + t) * HH + j] = h;
        }

        if (t != TT - 1) {      // grid barrier (counter zeroed by reset_kernel)
            target += 128;
            __syncthreads();
            if (tid == 0) {
                __threadfence();
                atomicAdd(&g_barcnt, 1u);
                while (*(volatile unsigned*)&g_barcnt < target) { }
                __threadfence();
            }
            __syncthreads();
        }
    }
}

// ---------------- reset barrier counter + zero h0 (per recurrence launch) ---
__global__ void reset_kernel() {
    unsigned t = blockIdx.x * blockDim.x + threadIdx.x;
    if (t == 0) g_barcnt = 0u;
    if (t < BB * HH) g_h[0][t] = 0.f;
}

// ---------------- launch ----------------------------------------------------
extern "C" void kernel_launch(void* const* d_in, const int* in_sizes, int n_in,
                              void* d_out, int out_size)
{
    const int*   x    = (const int*)  d_in[0];
    const float* emb  = (const float*)d_in[1];
    const float* Wih0 = (const float*)d_in[2];
    const float* Whh0 = (const float*)d_in[3];
    const float* bih0 = (const float*)d_in[4];
    const float* bhh0 = (const float*)d_in[5];
    const float* Wih1 = (const float*)d_in[6];
    const float* Whh1 = (const float*)d_in[7];
    const float* bih1 = (const float*)d_in[8];
    const float* bhh1 = (const float*)d_in[9];
    const float* Wout = (const float*)d_in[10];
    const float* bout = (const float*)d_in[11];
    float* out = (float*)d_out;

    float *pX0, *pXG, *pH0, *pH1;
    cudaGetSymbolAddress((void**)&pX0, g_X0);
    cudaGetSymbolAddress((void**)&pXG, g_XG);
    cudaGetSymbolAddress((void**)&pH0, g_H0);
    cudaGetSymbolAddress((void**)&pH1, g_H1);

    const int LSTM_SMEM = (32 * WS_STRIDE + 8 * WS_STRIDE) * 4;   // ~164.5 KB
    cudaFuncSetAttribute(lstm_kernel,
                         cudaFuncAttributeMaxDynamicSharedMemorySize, LSTM_SMEM);

    // 1) embedding
    embed_kernel<<<BT, 128>>>(x, emb);
    // 2) layer0 input GEMM: XG = X0 @ Wih0^T + bih0 + bhh0
    gemm_nt_kernel<<<dim3(H4 / 128, BT / 128), 512>>>(pX0, Wih0, bih0, bhh0, pXG, BT, H4, EE);
    // 3) layer0 recurrence
    reset_kernel<<<32, 256>>>();
    lstm_kernel<<<128, 256, LSTM_SMEM>>>(Whh0, pXG, pH0);
    // 4) layer1 input GEMM: XG = H0 @ Wih1^T + bih1 + bhh1
    gemm_nt_kernel<<<dim3(H4 / 128, BT / 128), 512>>>(pH0, Wih1, bih1, bhh1, pXG, BT, H4, HH);
    // 5) layer1 recurrence
    reset_kernel<<<32, 256>>>();
    lstm_kernel<<<128, 256, LSTM_SMEM>>>(Whh1, pXG, pH1);
    // 6) output GEMM: logits = H1 @ Wout^T + bout
    gemm_nt_kernel<<<dim3(CC / 128, BT / 128), 512>>>(pH1, Wout, bout, nullptr, out, BT, CC, HH);
}

// round 2
// speedup vs baseline: 1.0147x; 1.0147x over previous
#include <cuda_runtime.h>
#include <math.h>

typedef unsigned long long u64;

#define BT 4096     // B*T rows
#define TT 512
#define BB 8
#define EE 512
#define HH 1024
#define H4 4096
#define CC 32000
#define WS 1028     // padded row stride (floats): 1028 % 32 = 4 -> conflict-free

// ---------------- scratch (device globals; no allocation allowed) ----------
__device__ float g_X0[(size_t)BT * EE];        // embedded input   8 MB
__device__ float g_XG[(size_t)BT * H4];        // gate pre-acts   64 MB (reused)
__device__ float g_H0[(size_t)BT * HH];        // layer0 hidden   16 MB
__device__ float g_H1[(size_t)BT * HH];        // layer1 hidden   16 MB
__device__ float g_h[2][BB * HH];              // h double buffer
__device__ unsigned g_barcnt;                  // grid barrier counter

// ---------------- f32x2 helpers (Blackwell packed fp32: 2x FMA rate) -------
__device__ __forceinline__ void fma2(u64 &d, u64 a, u64 b) {
    asm("fma.rn.f32x2 %0, %1, %2, %0;" : "+l"(d) : "l"(a), "l"(b));
}
__device__ __forceinline__ float hsum2(u64 v) {
    float lo, hi;
    asm("mov.b64 {%0,%1}, %2;" : "=f"(lo), "=f"(hi) : "l"(v));
    return lo + hi;
}

// ---------------- embedding gather -----------------------------------------
__global__ void embed_kernel(const int* __restrict__ x, const float* __restrict__ emb) {
    int row = blockIdx.x;                 // 0..4095 = b*T+t
    int id = x[row];
    const float4* s = (const float4*)(emb + (size_t)id * EE);
    float4* d = (float4*)(g_X0 + (size_t)row * EE);
    int i = threadIdx.x;
    if (i < EE / 4) d[i] = s[i];
}

// ---------------- GEMM: C[M,N] = A[M,K] @ W[N,K]^T + b1[n] (+ b2[n]) -------
__global__ void __launch_bounds__(512, 1) gemm_nt_kernel(
    const float* __restrict__ A, const float* __restrict__ W,
    const float* __restrict__ b1, const float* __restrict__ b2,
    float* __restrict__ Cmat, int M, int N, int K)
{
    __shared__ float As[128][18];
    __shared__ float Ws2[128][18];
    const int t  = threadIdx.x;
    const int tx = t & 31;
    const int ty = t >> 5;
    const int m0 = blockIdx.y << 7;
    const int n0 = blockIdx.x << 7;

    u64 acc[8][4];
#pragma unroll
    for (int i = 0; i < 8; i++)
#pragma unroll
        for (int j = 0; j < 4; j++) acc[i][j] = 0ull;

    const int lrow = t >> 2;
    const int lc4  = (t & 3) << 2;
    const float* Ap = A + (size_t)(m0 + lrow) * K + lc4;
    const float* Wp = W + (size_t)(n0 + lrow) * K + lc4;

    float4 av = __ldg((const float4*)Ap);
    float4 wv = __ldg((const float4*)Wp);

    for (int k0 = 0; k0 < K; k0 += 16) {
        As[lrow][lc4 + 0] = av.x; As[lrow][lc4 + 1] = av.y;
        As[lrow][lc4 + 2] = av.z; As[lrow][lc4 + 3] = av.w;
        Ws2[lrow][lc4 + 0] = wv.x; Ws2[lrow][lc4 + 1] = wv.y;
        Ws2[lrow][lc4 + 2] = wv.z; Ws2[lrow][lc4 + 3] = wv.w;
        __syncthreads();

        if (k0 + 16 < K) {
            av = __ldg((const float4*)(Ap + k0 + 16));
            wv = __ldg((const float4*)(Wp + k0 + 16));
        }

#pragma unroll
        for (int kk = 0; kk < 16; kk += 2) {
            u64 a2[8], b2r[4];
#pragma unroll
            for (int i = 0; i < 8; i++)
                a2[i] = *(const u64*)&As[ty * 8 + i][kk];
#pragma unroll
            for (int j = 0; j < 4; j++)
                b2r[j] = *(const u64*)&Ws2[tx + (j << 5)][kk];
#pragma unroll
            for (int i = 0; i < 8; i++)
#pragma unroll
                for (int j = 0; j < 4; j++) fma2(acc[i][j], a2[i], b2r[j]);
        }
        __syncthreads();
    }

#pragma unroll
    for (int j = 0; j < 4; j++) {
        int n = n0 + tx + (j << 5);
        float bias = __ldg(&b1[n]) + (b2 ? __ldg(&b2[n]) : 0.f);
#pragma unroll
        for (int i = 0; i < 8; i++) {
            Cmat[(size_t)(m0 + ty * 8 + i) * N + n] = hsum2(acc[i][j]) + bias;
        }
    }
}

// ---------------- LSTM recurrence: persistent kernel, 512 threads ----------
// 128 blocks (1/SM, co-resident). Block owns 8 hidden units = 32 gate-rows of
// Whh kept in smem. Thread (half, r, b): half = tid>>8 (k-range split so each
// WARP covers one k-half: 4 rows x 8 batches), r = (tid>>3)&31, b = tid&7.
// Each thread computes a 512-long partial dot; pair (half 0/1) reduced via
// a tiny smem array. Gate nonlins fused in the combine stage; 64 threads do
// the cell update and publish h globally; custom grid barrier per step.
__global__ void __launch_bounds__(512, 1) lstm_kernel(
    const float* __restrict__ Whh,   // [4096, 1024]
    const float* __restrict__ XG,    // [(b*T+t), 4096] input pre-acts + biases
    float* __restrict__ Hout)        // [(b*T+t), 1024]
{
    extern __shared__ float smem[];
    float* ws = smem;                        // [32][WS]
    float* hs = smem + 32 * WS;              // [8][WS]
    __shared__ float ps[512];                // partial sums [r][b][half]
    __shared__ float gates[32][8];           // post-nonlinearity gate values
    __shared__ float c_s[64];                // cell state [unit][batch]

    const int tid = threadIdx.x;
    const int blk = blockIdx.x;

    // Load this block's 32 Whh rows into smem (once).
    for (int idx = tid; idx < 32 * 256; idx += 512) {
        int r  = idx >> 8;
        int c4 = (idx & 255) << 2;
        int gr = ((r >> 3) << 10) + (blk << 3) + (r & 7);
        float4 v = __ldg((const float4*)(Whh + (size_t)gr * HH + c4));
        *(float4*)&ws[r * WS + c4] = v;
    }
    if (tid < 64) c_s[tid] = 0.f;

    const int half = tid >> 8;
    const int r = (tid >> 3) & 31;
    const int b = tid & 7;
    const int G = r >> 3, u = r & 7;
    const int grow = (G << 10) + (blk << 3) + u;
    const float* wr = ws + r * WS + (half << 9);
    const float* hr = hs + b * WS + (half << 9);

    unsigned target = 0;
    for (int t = 0; t < TT; t++) {
        const int cur = t & 1;
        // Pull h (written by other SMs last step) into smem (bypass stale L1).
        for (int idx = tid; idx < 2048; idx += 512) {
            int bb = idx >> 8;
            int c4 = (idx & 255) << 2;
            float4 v = __ldcg((const float4*)&g_h[cur][bb * HH + c4]);
            *(float4*)&hs[bb * WS + c4] = v;
        }
        // Prefetch gate input early: its L2 latency hides under the dot.
        float gin = 0.f;
        if (tid < 256) gin = __ldg(&XG[(size_t)((b << 9) + t) * H4 + grow]);
        __syncthreads();

        u64 acc0 = 0ull, acc1 = 0ull;
#pragma unroll 4
        for (int k = 0; k < 512; k += 8) {
            ulonglong2 w0 = *(const ulonglong2*)(wr + k);
            ulonglong2 h0 = *(const ulonglong2*)(hr + k);
            ulonglong2 w1 = *(const ulonglong2*)(wr + k + 4);
            ulonglong2 h1 = *(const ulonglong2*)(hr + k + 4);
            fma2(acc0, w0.x, h0.x); fma2(acc1, w0.y, h0.y);
            fma2(acc0, w1.x, h1.x); fma2(acc1, w1.y, h1.y);
        }
        ps[(r << 4) + (b << 1) + half] = hsum2(acc0) + hsum2(acc1);
        __syncthreads();

        if (tid < 256) {   // combine halves + nonlinearity; (r,b) match tid
            float gsum = ps[tid << 1] + ps[(tid << 1) + 1] + gin;
            gates[r][b] = (G == 2) ? tanhf(gsum)
                                   : 1.f / (1.f + expf(-gsum));
        }
        __syncthreads();

        if (tid < 64) {    // cell update: unit uu, batch bb
            int uu = tid >> 3, bb = tid & 7;
            float c = gates[8 + uu][bb] * c_s[tid] + gates[uu][bb] * gates[16 + uu][bb];
            c_s[tid] = c;
            float h = gates[24 + uu][bb] * tanhf(c);
            int j = (blk << 3) + uu;
            g_h[cur ^ 1][bb * HH + j] = h;
            Hout[(size_t)((bb << 9) + t) * HH + j] = h;
        }

        if (t != TT - 1) {      // grid barrier (counter zeroed by reset_kernel)
            target += 128;
            __syncthreads();
            if (tid == 0) {
                __threadfence();
                atomicAdd(&g_barcnt, 1u);
                while (*(volatile unsigned*)&g_barcnt < target) { }
                __threadfence();
            }
            __syncthreads();
        }
    }
}

// ---------------- reset barrier counter + zero h0 (per recurrence launch) ---
__global__ void reset_kernel() {
    unsigned t = blockIdx.x * blockDim.x + threadIdx.x;
    if (t == 0) g_barcnt = 0u;
    if (t < BB * HH) g_h[0][t] = 0.f;
}

// ---------------- launch ----------------------------------------------------
extern "C" void kernel_launch(void* const* d_in, const int* in_sizes, int n_in,
                              void* d_out, int out_size)
{
    const int*   x    = (const int*)  d_in[0];
    const float* emb  = (const float*)d_in[1];
    const float* Wih0 = (const float*)d_in[2];
    const float* Whh0 = (const float*)d_in[3];
    const float* bih0 = (const float*)d_in[4];
    const float* bhh0 = (const float*)d_in[5];
    const float* Wih1 = (const float*)d_in[6];
    const float* Whh1 = (const float*)d_in[7];
    const float* bih1 = (const float*)d_in[8];
    const float* bhh1 = (const float*)d_in[9];
    const float* Wout = (const float*)d_in[10];
    const float* bout = (const float*)d_in[11];
    float* out = (float*)d_out;

    float *pX0, *pXG, *pH0, *pH1;
    cudaGetSymbolAddress((void**)&pX0, g_X0);
    cudaGetSymbolAddress((void**)&pXG, g_XG);
    cudaGetSymbolAddress((void**)&pH0, g_H0);
    cudaGetSymbolAddress((void**)&pH1, g_H1);

    const int LSTM_SMEM = (32 * WS + 8 * WS) * 4;   // ~164.5 KB dynamic
    cudaFuncSetAttribute(lstm_kernel,
                         cudaFuncAttributeMaxDynamicSharedMemorySize, LSTM_SMEM);

    // 1) embedding
    embed_kernel<<<BT, 128>>>(x, emb);
    // 2) layer0 input GEMM: XG = X0 @ Wih0^T + bih0 + bhh0
    gemm_nt_kernel<<<dim3(H4 / 128, BT / 128), 512>>>(pX0, Wih0, bih0, bhh0, pXG, BT, H4, EE);
    // 3) layer0 recurrence
    reset_kernel<<<32, 256>>>();
    lstm_kernel<<<128, 512, LSTM_SMEM>>>(Whh0, pXG, pH0);
    // 4) layer1 input GEMM: XG = H0 @ Wih1^T + bih1 + bhh1
    gemm_nt_kernel<<<dim3(H4 / 128, BT / 128), 512>>>(pH0, Wih1, bih1, bhh1, pXG, BT, H4, HH);
    // 5) layer1 recurrence
    reset_kernel<<<32, 256>>>();
    lstm_kernel<<<128, 512, LSTM_SMEM>>>(Whh1, pXG, pH1);
    // 6) output GEMM: logits = H1 @ Wout^T + bout
    gemm_nt_kernel<<<dim3(CC / 128, BT / 128), 512>>>(pH1, Wout, bout, nullptr, out, BT, CC, HH);
}

// round 3
// speedup vs baseline: 1.4010x; 1.3807x over previous
#include <cuda_runtime.h>
#include <math.h>

typedef unsigned long long u64;

#define BT 4096     // B*T rows
#define TT 512
#define BB 8
#define EE 512
#define HH 1024
#define H4 4096
#define CC 32000

// ---------------- scratch (device globals; no allocation allowed) ----------
__device__ float g_X0[(size_t)BT * EE];        // embedded input   8 MB
__device__ float g_XG[(size_t)BT * H4];        // gate pre-acts   64 MB (reused)
__device__ float g_H0[(size_t)BT * HH];        // layer0 hidden   16 MB
__device__ float g_H1[(size_t)BT * HH];        // layer1 hidden   16 MB
__device__ float g_h[2][BB * HH];              // h double buffer
__device__ unsigned g_barcnt;                  // grid barrier counter

// ---------------- f32x2 helpers (Blackwell packed fp32: 2x FMA rate) -------
__device__ __forceinline__ void fma2(u64 &d, u64 a, u64 b) {
    asm("fma.rn.f32x2 %0, %1, %2, %0;" : "+l"(d) : "l"(a), "l"(b));
}
__device__ __forceinline__ float hsum2(u64 v) {
    float lo, hi;
    asm("mov.b64 {%0,%1}, %2;" : "=f"(lo), "=f"(hi) : "l"(v));
    return lo + hi;
}

// ---------------- embedding gather -----------------------------------------
__global__ void embed_kernel(const int* __restrict__ x, const float* __restrict__ emb) {
    int row = blockIdx.x;                 // 0..4095 = b*T+t
    int id = x[row];
    const float4* s = (const float4*)(emb + (size_t)id * EE);
    float4* d = (float4*)(g_X0 + (size_t)row * EE);
    int i = threadIdx.x;
    if (i < EE / 4) d[i] = s[i];
}

// ---------------- GEMM: C[M,N] = A[M,K] @ W[N,K]^T + b1[n] (+ b2[n]) -------
// BM=128, BN=64, BK=16, 256 threads, thread tile 8x4, 2 CTAs per SM so one
// block's syncthreads/prefetch bubbles are filled by the other's FMAs.
__global__ void __launch_bounds__(256, 2) gemm_nt_kernel(
    const float* __restrict__ A, const float* __restrict__ W,
    const float* __restrict__ b1, const float* __restrict__ b2,
    float* __restrict__ Cmat, int M, int N, int K)
{
    __shared__ float As[128][18];
    __shared__ float Ws2[64][18];
    const int t  = threadIdx.x;
    const int tx = t & 15;          // n: cols tx, tx+16, tx+32, tx+48
    const int ty = t >> 4;          // m: rows ty*8 .. ty*8+7
    const int m0 = blockIdx.y << 7;
    const int n0 = blockIdx.x << 6;

    u64 acc[8][4];
#pragma unroll
    for (int i = 0; i < 8; i++)
#pragma unroll
        for (int j = 0; j < 4; j++) acc[i][j] = 0ull;

    // loaders: A tile 128x16 (2 float4/thread), W tile 64x16 (1 float4/thread)
    const int arow = t >> 1, ac = (t & 1) << 3;
    const int wrow = t >> 2, wc = (t & 3) << 2;
    const float* Ap = A + (size_t)(m0 + arow) * K + ac;
    const float* Wp = W + (size_t)(n0 + wrow) * K + wc;

    float4 av0 = __ldg((const float4*)Ap);
    float4 av1 = __ldg((const float4*)(Ap + 4));
    float4 wv  = __ldg((const float4*)Wp);

    for (int k0 = 0; k0 < K; k0 += 16) {
        As[arow][ac + 0] = av0.x; As[arow][ac + 1] = av0.y;
        As[arow][ac + 2] = av0.z; As[arow][ac + 3] = av0.w;
        As[arow][ac + 4] = av1.x; As[arow][ac + 5] = av1.y;
        As[arow][ac + 6] = av1.z; As[arow][ac + 7] = av1.w;
        Ws2[wrow][wc + 0] = wv.x; Ws2[wrow][wc + 1] = wv.y;
        Ws2[wrow][wc + 2] = wv.z; Ws2[wrow][wc + 3] = wv.w;
        __syncthreads();

        if (k0 + 16 < K) {          // prefetch next tile
            av0 = __ldg((const float4*)(Ap + k0 + 16));
            av1 = __ldg((const float4*)(Ap + k0 + 20));
            wv  = __ldg((const float4*)(Wp + k0 + 16));
        }

#pragma unroll
        for (int kk = 0; kk < 16; kk += 2) {
            u64 a2[8], b2r[4];
#pragma unroll
            for (int i = 0; i < 8; i++)
                a2[i] = *(const u64*)&As[ty * 8 + i][kk];
#pragma unroll
            for (int j = 0; j < 4; j++)
                b2r[j] = *(const u64*)&Ws2[tx + (j << 4)][kk];
#pragma unroll
            for (int i = 0; i < 8; i++)
#pragma unroll
                for (int j = 0; j < 4; j++) fma2(acc[i][j], a2[i], b2r[j]);
        }
        __syncthreads();
    }

#pragma unroll
    for (int j = 0; j < 4; j++) {
        int n = n0 + tx + (j << 4);
        float bias = __ldg(&b1[n]) + (b2 ? __ldg(&b2[n]) : 0.f);
#pragma unroll
        for (int i = 0; i < 8; i++) {
            Cmat[(size_t)(m0 + ty * 8 + i) * N + n] = hsum2(acc[i][j]) + bias;
        }
    }
}

// ---------------- LSTM recurrence: persistent kernel, 512 threads ----------
// 128 blocks (1/SM, co-resident; custom grid barrier). Block owns 8 hidden
// units = 32 gate-rows of Whh. Thread (kc = warp = tid>>5, r = tid&31) holds
// Whh[gate-row r][kc*64 .. kc*64+64) permanently in 64 REGISTERS. Per step,
// per batch b, it does a 64-long dot against smem h using uniform (warp-
// broadcast) LDS.128 loads -> fma-pipe bound, ~2048 cyc/step.
__device__ __forceinline__ float sigmoidf_(float x) { return 1.f / (1.f + expf(-x)); }

__global__ void __launch_bounds__(512, 1) lstm_kernel(
    const float* __restrict__ Whh,   // [4096, 1024]
    const float* __restrict__ XG,    // [(b*T+t), 4096] input pre-acts + biases
    float* __restrict__ Hout)        // [(b*T+t), 1024]
{
    extern __shared__ float dsm[];
    float* hs = dsm;                 // [8][1024]  = 32 KB
    float* ps = dsm + BB * HH;       // [8][16][32] = 16 KB partials
    __shared__ float gates[32][8];
    __shared__ float c_s[64];

    const int tid = threadIdx.x;
    const int blk = blockIdx.x;
    const int kc  = tid >> 5;        // k-chunk (== warp id), 0..15
    const int r   = tid & 31;        // gate-row within block's 32

    // Load this thread's 64 weights into registers (held across all steps).
    u64 wreg[32];
    {
        const int gr = ((r >> 3) << 10) + (blk << 3) + (r & 7);
        const ulonglong2* wp =
            (const ulonglong2*)(Whh + (size_t)gr * HH + (kc << 6));
#pragma unroll
        for (int p = 0; p < 16; p++) {
            ulonglong2 v = __ldg(&wp[p]);
            wreg[2 * p] = v.x; wreg[2 * p + 1] = v.y;
        }
    }
    if (tid < 64) c_s[tid] = 0.f;

    // reducer-thread mapping (tid < 256): rr = tid&31, bb = tid>>5
    const int rr = tid & 31, bb = tid >> 5;
    const int grow_red = ((rr >> 3) << 10) + (blk << 3) + (rr & 7);

    unsigned target = 0;
    for (int t = 0; t < TT; t++) {
        const int cur = t & 1;
        // Gather full h (written by all SMs last step) into smem, bypass L1.
        {
            const float4* src = (const float4*)g_h[cur];
            float4* dst = (float4*)hs;
#pragma unroll
            for (int idx = tid; idx < (BB * HH) / 4; idx += 512)
                dst[idx] = __ldcg(&src[idx]);
        }
        // Prefetch gate input (DRAM latency hides under the dot).
        float gin = 0.f;
        if (tid < 256)
            gin = __ldg(&XG[(size_t)((bb << 9) + t) * H4 + grow_red]);
        __syncthreads();

        // 8 batches x 64-long dot, weights in regs, h uniform LDS.
#pragma unroll
        for (int b = 0; b < 8; b++) {
            const ulonglong2* hp =
                (const ulonglong2*)(hs + (b << 10) + (kc << 6));
            u64 acc0 = 0ull, acc1 = 0ull;
#pragma unroll
            for (int p = 0; p < 16; p++) {
                ulonglong2 hv = hp[p];
                fma2(acc0, wreg[2 * p], hv.x);
                fma2(acc1, wreg[2 * p + 1], hv.y);
            }
            ps[(b << 9) + (kc << 5) + r] = hsum2(acc0) + hsum2(acc1);
        }
        __syncthreads();

        if (tid < 256) {   // combine 16 partials + nonlinearity for (rr, bb)
            float s = gin;
#pragma unroll
            for (int k2 = 0; k2 < 16; k2++)
                s += ps[(bb << 9) + (k2 << 5) + rr];
            gates[rr][bb] = ((rr >> 3) == 2) ? tanhf(s) : sigmoidf_(s);
        }
        __syncthreads();

        if (tid < 64) {    // cell update: unit uu, batch bu
            int uu = tid >> 3, bu = tid & 7;
            float c = gates[8 + uu][bu] * c_s[tid] + gates[uu][bu] * gates[16 + uu][bu];
            c_s[tid] = c;
            float h = gates[24 + uu][bu] * tanhf(c);
            int j = (blk << 3) + uu;
            g_h[cur ^ 1][bu * HH + j] = h;
            Hout[(size_t)((bu << 9) + t) * HH + j] = h;
            __threadfence();            // release: h visible before barrier
        }

        if (t != TT - 1) {      // grid barrier (counter zeroed by reset_kernel)
            target += 128;
            __syncthreads();
            if (tid == 0) {
                atomicAdd(&g_barcnt, 1u);
                while (*(volatile unsigned*)&g_barcnt < target) { }
                __threadfence();        // acquire
            }
            __syncthreads();
        }
    }
}

// ---------------- reset barrier counter + zero h0 (per recurrence launch) ---
__global__ void reset_kernel() {
    unsigned t = blockIdx.x * blockDim.x + threadIdx.x;
    if (t == 0) g_barcnt = 0u;
    if (t < BB * HH) g_h[0][t] = 0.f;
}

// ---------------- launch ----------------------------------------------------
extern "C" void kernel_launch(void* const* d_in, const int* in_sizes, int n_in,
                              void* d_out, int out_size)
{
    const int*   x    = (const int*)  d_in[0];
    const float* emb  = (const float*)d_in[1];
    const float* Wih0 = (const float*)d_in[2];
    const float* Whh0 = (const float*)d_in[3];
    const float* bih0 = (const float*)d_in[4];
    const float* bhh0 = (const float*)d_in[5];
    const float* Wih1 = (const float*)d_in[6];
    const float* Whh1 = (const float*)d_in[7];
    const float* bih1 = (const float*)d_in[8];
    const float* bhh1 = (const float*)d_in[9];
    const float* Wout = (const float*)d_in[10];
    const float* bout = (const float*)d_in[11];
    float* out = (float*)d_out;

    float *pX0, *pXG, *pH0, *pH1;
    cudaGetSymbolAddress((void**)&pX0, g_X0);
    cudaGetSymbolAddress((void**)&pXG, g_XG);
    cudaGetSymbolAddress((void**)&pH0, g_H0);
    cudaGetSymbolAddress((void**)&pH1, g_H1);

    const int LSTM_SMEM = (BB * HH + BB * 16 * 32) * 4;   // 48 KB dynamic
    cudaFuncSetAttribute(lstm_kernel,
                         cudaFuncAttributeMaxDynamicSharedMemorySize, LSTM_SMEM);

    // 1) embedding
    embed_kernel<<<BT, 128>>>(x, emb);
    // 2) layer0 input GEMM: XG = X0 @ Wih0^T + bih0 + bhh0
    gemm_nt_kernel<<<dim3(H4 / 64, BT / 128), 256>>>(pX0, Wih0, bih0, bhh0, pXG, BT, H4, EE);
    // 3) layer0 recurrence
    reset_kernel<<<32, 256>>>();
    lstm_kernel<<<128, 512, LSTM_SMEM>>>(Whh0, pXG, pH0);
    // 4) layer1 input GEMM: XG = H0 @ Wih1^T + bih1 + bhh1
    gemm_nt_kernel<<<dim3(H4 / 64, BT / 128), 256>>>(pH0, Wih1, bih1, bhh1, pXG, BT, H4, HH);
    // 5) layer1 recurrence
    reset_kernel<<<32, 256>>>();
    lstm_kernel<<<128, 512, LSTM_SMEM>>>(Whh1, pXG, pH1);
    // 6) output GEMM: logits = H1 @ Wout^T + bout
    gemm_nt_kernel<<<dim3(CC / 64, BT / 128), 256>>>(pH1, Wout, bout, nullptr, out, BT, CC, HH);
}

// round 5
// speedup vs baseline: 2.3606x; 1.6849x over previous
#include <cuda_runtime.h>
#include <cuda_bf16.h>
#include <math.h>
#include <stdint.h>

typedef unsigned long long u64;

#define BT 4096     // B*T rows
#define TT 512
#define BB 8
#define EE 512
#define HH 1024
#define H4 4096
#define CC 32000

// ---------------- scratch (device globals; no allocation allowed) ----------
__device__ float g_XG[(size_t)BT * H4];        // gate pre-acts   64 MB
__device__ float g_H0[(size_t)BT * HH];        // layer0 hidden   16 MB
__device__ float g_H1[(size_t)BT * HH];        // layer1 hidden   16 MB
__device__ float g_h[2][BB * HH];              // h double buffer
__device__ unsigned g_barcnt;                  // grid barrier counter
__device__ __align__(16) __nv_bfloat16 g_Whi[(size_t)CC * HH];  // 64 MB
__device__ __align__(16) __nv_bfloat16 g_Wlo[(size_t)CC * HH];  // 64 MB
__device__ __align__(16) __nv_bfloat16 g_Ahi[(size_t)BT * HH];  //  8 MB
__device__ __align__(16) __nv_bfloat16 g_Alo[(size_t)BT * HH];  //  8 MB

// ---------------- fp32x2 helpers (LSTM recurrence) --------------------------
__device__ __forceinline__ void fma2(u64 &d, u64 a, u64 b) {
    asm("fma.rn.f32x2 %0, %1, %2, %0;" : "+l"(d) : "l"(a), "l"(b));
}
__device__ __forceinline__ float hsum2(u64 v) {
    float lo, hi;
    asm("mov.b64 {%0,%1}, %2;" : "=f"(lo), "=f"(hi) : "l"(v));
    return lo + hi;
}

// ---------------- small helpers ---------------------------------------------
__device__ __forceinline__ uint32_t smem_u32(const void* p) {
    uint32_t a;
    asm("{ .reg .u64 t; cvta.to.shared.u64 t, %1; cvt.u32.u64 %0, t; }"
        : "=r"(a) : "l"(p));
    return a;
}
// pack two consecutive-memory elements (e0 low half, e1 high half)
__device__ __forceinline__ uint32_t packbf(float e0, float e1) {
    uint32_t r;
    asm("cvt.rn.bf16x2.f32 %0, %1, %2;" : "=r"(r) : "f"(e1), "f"(e0));
    return r;
}
__device__ __forceinline__ void cpa16(uint32_t s, const void* g) {
    asm volatile("cp.async.cg.shared.global [%0], [%1], 16;" :: "r"(s), "l"(g));
}
#define CPA_COMMIT() asm volatile("cp.async.commit_group;" ::: "memory")
#define CPA_WAIT1()  asm volatile("cp.async.wait_group 1;"  ::: "memory")
#define CPA_WAIT0()  asm volatile("cp.async.wait_group 0;"  ::: "memory")

#define LDSM4(r, a) \
    asm volatile("ldmatrix.sync.aligned.m8n8.x4.shared.b16 {%0,%1,%2,%3}, [%4];" \
        : "=r"((r)[0]), "=r"((r)[1]), "=r"((r)[2]), "=r"((r)[3]) : "r"(a))

__device__ __forceinline__ void mma_bf(float* d, const uint32_t* a, const uint32_t* b) {
    asm volatile(
        "mma.sync.aligned.m16n8k16.row.col.f32.bf16.bf16.f32 "
        "{%0,%1,%2,%3}, {%4,%5,%6,%7}, {%8,%9}, {%0,%1,%2,%3};"
        : "+f"(d[0]), "+f"(d[1]), "+f"(d[2]), "+f"(d[3])
        : "r"(a[0]), "r"(a[1]), "r"(a[2]), "r"(a[3]), "r"(b[0]), "r"(b[1]));
}

// ---------------- hi/lo bf16 split kernels ----------------------------------
__global__ void split_kernel(const float* __restrict__ src,
                             __nv_bfloat16* __restrict__ hi,
                             __nv_bfloat16* __restrict__ lo, int n4) {
    int i = blockIdx.x * 256 + threadIdx.x;
    if (i >= n4) return;
    float4 v = __ldg((const float4*)src + i);
    float hx = __bfloat162float(__float2bfloat16(v.x));
    float hy = __bfloat162float(__float2bfloat16(v.y));
    float hz = __bfloat162float(__float2bfloat16(v.z));
    float hw = __bfloat162float(__float2bfloat16(v.w));
    uint2 H, L;
    H.x = packbf(hx, hy);         H.y = packbf(hz, hw);
    L.x = packbf(v.x - hx, v.y - hy);
    L.y = packbf(v.z - hz, v.w - hw);
    ((uint2*)hi)[i] = H;
    ((uint2*)lo)[i] = L;
}

// embedding gather -> split bf16 directly into A arrays (K = EE)
__global__ void embed_kernel(const int* __restrict__ x, const float* __restrict__ emb) {
    int row = blockIdx.x;
    int id = __ldg(&x[row]);
    int i = threadIdx.x;                  // 128 threads = EE/4 float4s
    float4 v = __ldg((const float4*)(emb + (size_t)id * EE) + i);
    float hx = __bfloat162float(__float2bfloat16(v.x));
    float hy = __bfloat162float(__float2bfloat16(v.y));
    float hz = __bfloat162float(__float2bfloat16(v.z));
    float hw = __bfloat162float(__float2bfloat16(v.w));
    uint2 H, L;
    H.x = packbf(hx, hy);         H.y = packbf(hz, hw);
    L.x = packbf(v.x - hx, v.y - hy);
    L.y = packbf(v.z - hz, v.w - hw);
    size_t idx = (size_t)row * (EE / 4) + i;
    ((uint2*)g_Ahi)[idx] = H;
    ((uint2*)g_Alo)[idx] = L;
}

// ---------------- bf16 split-MMA GEMM ---------------------------------------
// C[M,N] = A[M,K] @ W[N,K]^T + b1 (+ b2) via D += Ah*Wh + Ah*Wl + Al*Wh.
// CTA 128x128, BK=32, 256 threads (8 warps, warp tile 64x32),
// cp.async 2-stage pipeline, 80B-padded smem rows (conflict-free ldmatrix).
#define RS 40                   // smem row stride in bf16 (80 bytes)
#define SSZ (128 * RS * 2)      // 10240 B: one array, one stage
#define GSMEM (8 * SSZ)         // 4 arrays x 2 stages = 81920 B

__device__ __forceinline__ void ld_stage(uint32_t sb, int s,
    const __nv_bfloat16* __restrict__ Ah, const __nv_bfloat16* __restrict__ Al,
    const __nv_bfloat16* __restrict__ Wh, const __nv_bfloat16* __restrict__ Wl,
    int m0, int n0, int K, int k0, int tid)
{
    const int r  = tid >> 2;           // row 0..63
    const int kb = (tid & 3) << 3;     // k offset in elements (0,8,16,24)
    const uint32_t so = sb + (uint32_t)s * SSZ + r * 80 + (kb << 1);
    const size_t gA = (size_t)(m0 + r) * K + k0 + kb;
    const size_t gW = (size_t)(n0 + r) * K + k0 + kb;
    const size_t g64 = (size_t)64 * K;
    cpa16(so,                  Ah + gA);
    cpa16(so + 64 * 80,        Ah + gA + g64);
    cpa16(so + 2 * SSZ,            Al + gA);
    cpa16(so + 2 * SSZ + 64 * 80,  Al + gA + g64);
    cpa16(so + 4 * SSZ,            Wh + gW);
    cpa16(so + 4 * SSZ + 64 * 80,  Wh + gW + g64);
    cpa16(so + 6 * SSZ,            Wl + gW);
    cpa16(so + 6 * SSZ + 64 * 80,  Wl + gW + g64);
}

__device__ __forceinline__ void comp_stage(uint32_t sb, int s, int lane,
                                           int wm, int wn, float (*d)[4][4])
{
    const uint32_t base = sb + (uint32_t)s * SSZ;
    // A frag addr pattern: lanes 0-15 rows 0-15 @k0, lanes 16-31 same rows @k0+8
    const uint32_t aoff = (lane & 15) * 80 + ((lane >> 4) << 4);
    // B frag addr pattern: lanes 0-7 rows0-7@k0, 8-15 rows0-7@k+8, 16-23 rows8-15@k0, 24-31 rows8-15@k+8
    const uint32_t boff = ((((lane >> 4) << 3) + (lane & 7)) * 80) + (((lane >> 3) & 1) << 4);
#pragma unroll
    for (int ks = 0; ks < 2; ks++) {
        const uint32_t kb = ks << 5;   // 16 bf16 = 32 B
        uint32_t ah[4][4], al[4][4], bh[2][4], bl[2][4];
#pragma unroll
        for (int mt = 0; mt < 4; mt++) {
            uint32_t a = base + (wm + mt * 16) * 80 + aoff + kb;
            LDSM4(ah[mt], a);
            LDSM4(al[mt], a + 2 * SSZ);
        }
#pragma unroll
        for (int g = 0; g < 2; g++) {
            uint32_t a = base + 4 * SSZ + (wn + g * 16) * 80 + boff + kb;
            LDSM4(bh[g], a);
            LDSM4(bl[g], a + 2 * SSZ);
        }
#pragma unroll
        for (int mt = 0; mt < 4; mt++)
#pragma unroll
            for (int nt = 0; nt < 4; nt++) {
                const uint32_t* ph = &bh[nt >> 1][(nt & 1) << 1];
                const uint32_t* pl = &bl[nt >> 1][(nt & 1) << 1];
                mma_bf(d[mt][nt], ah[mt], ph);
                mma_bf(d[mt][nt], ah[mt], pl);
                mma_bf(d[mt][nt], al[mt], ph);
            }
    }
}

__global__ void __launch_bounds__(256) mma_gemm(
    const __nv_bfloat16* __restrict__ Ahi, const __nv_bfloat16* __restrict__ Alo,
    const __nv_bfloat16* __restrict__ Whi, const __nv_bfloat16* __restrict__ Wlo,
    const float* __restrict__ b1, const float* __restrict__ b2,
    float* __restrict__ C, int M, int N, int K)
{
    extern __shared__ char sm[];
    const uint32_t sb = smem_u32(sm);
    const int tid = threadIdx.x, lane = tid & 31, wid = tid >> 5;
    const int m0 = blockIdx.x << 7, n0 = blockIdx.y << 7;
    const int wm = (wid >> 2) << 6, wn = (wid & 3) << 5;

    float d[4][4][4];
#pragma unroll
    for (int i = 0; i < 4; i++)
#pragma unroll
        for (int j = 0; j < 4; j++)
#pragma unroll
            for (int k = 0; k < 4; k++) d[i][j][k] = 0.f;

    const int KT = K >> 5;
    ld_stage(sb, 0, Ahi, Alo, Whi, Wlo, m0, n0, K, 0, tid);
    CPA_COMMIT();
    for (int kt = 0; kt < KT; kt++) {
        if (kt + 1 < KT) {
            ld_stage(sb, (kt + 1) & 1, Ahi, Alo, Whi, Wlo, m0, n0, K, (kt + 1) << 5, tid);
            CPA_COMMIT();
            CPA_WAIT1();
        } else {
            CPA_WAIT0();
        }
        __syncthreads();
        comp_stage(sb, kt & 1, lane, wm, wn, d);
        __syncthreads();
    }

    // epilogue: frag (row = lane>>2 [+8], col = 2*(lane&3) [+1])
#pragma unroll
    for (int mt = 0; mt < 4; mt++) {
        const int row0 = m0 + wm + mt * 16 + (lane >> 2);
#pragma unroll
        for (int nt = 0; nt < 4; nt++) {
            const int col = n0 + wn + nt * 8 + ((lane & 3) << 1);
            float bb0 = __ldg(&b1[col]);
            float bb1 = __ldg(&b1[col + 1]);
            if (b2) { bb0 += __ldg(&b2[col]); bb1 += __ldg(&b2[col + 1]); }
            float2 v0 = { d[mt][nt][0] + bb0, d[mt][nt][1] + bb1 };
            float2 v1 = { d[mt][nt][2] + bb0, d[mt][nt][3] + bb1 };
            *(float2*)&C[(size_t)row0 * N + col]       = v0;
            *(float2*)&C[(size_t)(row0 + 8) * N + col] = v1;
        }
    }
}

// ---------------- LSTM recurrence: persistent kernel, 512 threads ----------
__device__ __forceinline__ float sigmoidf_(float x) { return 1.f / (1.f + expf(-x)); }

__global__ void __launch_bounds__(512, 1) lstm_kernel(
    const float* __restrict__ Whh,   // [4096, 1024]
    const float* __restrict__ XG,    // [(b*T+t), 4096] input pre-acts + biases
    float* __restrict__ Hout)        // [(b*T+t), 1024]
{
    extern __shared__ float dsm[];
    float* hs = dsm;                 // [8][1024]  = 32 KB
    float* ps = dsm + BB * HH;       // [8][16][32] = 16 KB partials
    __shared__ float gates[32][8];
    __shared__ float c_s[64];

    const int tid = threadIdx.x;
    const int blk = blockIdx.x;
    const int kc  = tid >> 5;        // k-chunk (== warp id), 0..15
    const int r   = tid & 31;        // gate-row within block's 32

    u64 wreg[32];
    {
        const int gr = ((r >> 3) << 10) + (blk << 3) + (r & 7);
        const ulonglong2* wp =
            (const ulonglong2*)(Whh + (size_t)gr * HH + (kc << 6));
#pragma unroll
        for (int p = 0; p < 16; p++) {
            ulonglong2 v = __ldg(&wp[p]);
            wreg[2 * p] = v.x; wreg[2 * p + 1] = v.y;
        }
    }
    if (tid < 64) c_s[tid] = 0.f;

    const int rr = tid & 31, bb = tid >> 5;
    const int grow_red = ((rr >> 3) << 10) + (blk << 3) + (rr & 7);

    unsigned target = 0;
    for (int t = 0; t < TT; t++) {
        const int cur = t & 1;
        {
            const float4* src = (const float4*)g_h[cur];
            float4* dst = (float4*)hs;
#pragma unroll
            for (int idx = tid; idx < (BB * HH) / 4; idx += 512)
                dst[idx] = __ldcg(&src[idx]);
        }
        float gin = 0.f;
        if (tid < 256)
            gin = __ldg(&XG[(size_t)((bb << 9) + t) * H4 + grow_red]);
        __syncthreads();

#pragma unroll
        for (int b = 0; b < 8; b++) {
            const ulonglong2* hp =
                (const ulonglong2*)(hs + (b << 10) + (kc << 6));
            u64 acc0 = 0ull, acc1 = 0ull;
#pragma unroll
            for (int p = 0; p < 16; p++) {
                ulonglong2 hv = hp[p];
                fma2(acc0, wreg[2 * p], hv.x);
                fma2(acc1, wreg[2 * p + 1], hv.y);
            }
            ps[(b << 9) + (kc << 5) + r] = hsum2(acc0) + hsum2(acc1);
        }
        __syncthreads();

        if (tid < 256) {
            float s = gin;
#pragma unroll
            for (int k2 = 0; k2 < 16; k2++)
                s += ps[(bb << 9) + (k2 << 5) + rr];
            gates[rr][bb] = ((rr >> 3) == 2) ? tanhf(s) : sigmoidf_(s);
        }
        __syncthreads();

        if (tid < 64) {
            int uu = tid >> 3, bu = tid & 7;
            float c = gates[8 + uu][bu] * c_s[tid] + gates[uu][bu] * gates[16 + uu][bu];
            c_s[tid] = c;
            float h = gates[24 + uu][bu] * tanhf(c);
            int j = (blk << 3) + uu;
            g_h[cur ^ 1][bu * HH + j] = h;
            Hout[(size_t)((bu << 9) + t) * HH + j] = h;
            __threadfence();
        }

        if (t != TT - 1) {
            target += 128;
            __syncthreads();
            if (tid == 0) {
                atomicAdd(&g_barcnt, 1u);
                while (*(volatile unsigned*)&g_barcnt < target) { }
                __threadfence();
            }
            __syncthreads();
        }
    }
}

__global__ void reset_kernel() {
    unsigned t = blockIdx.x * blockDim.x + threadIdx.x;
    if (t == 0) g_barcnt = 0u;
    if (t < BB * HH) g_h[0][t] = 0.f;
}

// ---------------- launch ----------------------------------------------------
extern "C" void kernel_launch(void* const* d_in, const int* in_sizes, int n_in,
                              void* d_out, int out_size)
{
    const int*   x    = (const int*)  d_in[0];
    const float* emb  = (const float*)d_in[1];
    const float* Wih0 = (const float*)d_in[2];
    const float* Whh0 = (const float*)d_in[3];
    const float* bih0 = (const float*)d_in[4];
    const float* bhh0 = (const float*)d_in[5];
    const float* Wih1 = (const float*)d_in[6];
    const float* Whh1 = (const float*)d_in[7];
    const float* bih1 = (const float*)d_in[8];
    const float* bhh1 = (const float*)d_in[9];
    const float* Wout = (const float*)d_in[10];
    const float* bout = (const float*)d_in[11];
    float* out = (float*)d_out;

    float *pXG, *pH0, *pH1;
    __nv_bfloat16 *pWhi, *pWlo, *pAhi, *pAlo;
    cudaGetSymbolAddress((void**)&pXG, g_XG);
    cudaGetSymbolAddress((void**)&pH0, g_H0);
    cudaGetSymbolAddress((void**)&pH1, g_H1);
    cudaGetSymbolAddress((void**)&pWhi, g_Whi);
    cudaGetSymbolAddress((void**)&pWlo, g_Wlo);
    cudaGetSymbolAddress((void**)&pAhi, g_Ahi);
    cudaGetSymbolAddress((void**)&pAlo, g_Alo);

    const int LSTM_SMEM = (BB * HH + BB * 16 * 32) * 4;   // 48 KB dynamic
    cudaFuncSetAttribute(lstm_kernel,
                         cudaFuncAttributeMaxDynamicSharedMemorySize, LSTM_SMEM);
    cudaFuncSetAttribute(mma_gemm,
                         cudaFuncAttributeMaxDynamicSharedMemorySize, GSMEM);

    // 1) embedding (writes split bf16 X0 into Ahi/Alo)
    embed_kernel<<<BT, 128>>>(x, emb);
    // 2) layer0 input GEMM: XG = X0 @ Wih0^T + bih0 + bhh0
    {
        int n4 = (H4 * EE) / 4;
        split_kernel<<<(n4 + 255) / 256, 256>>>(Wih0, pWhi, pWlo, n4);
        mma_gemm<<<dim3(BT / 128, H4 / 128), 256, GSMEM>>>(
            pAhi, pAlo, pWhi, pWlo, bih0, bhh0, pXG, BT, H4, EE);
    }
    // 3) layer0 recurrence
    reset_kernel<<<32, 256>>>();
    lstm_kernel<<<128, 512, LSTM_SMEM>>>(Whh0, pXG, pH0);
    // 4) layer1 input GEMM: XG = H0 @ Wih1^T + bih1 + bhh1
    {
        int n4a = (BT * HH) / 4, n4w = (H4 * HH) / 4;
        split_kernel<<<(n4a + 255) / 256, 256>>>(pH0, pAhi, pAlo, n4a);
        split_kernel<<<(n4w + 255) / 256, 256>>>(Wih1, pWhi, pWlo, n4w);
        mma_gemm<<<dim3(BT / 128, H4 / 128), 256, GSMEM>>>(
            pAhi, pAlo, pWhi, pWlo, bih1, bhh1, pXG, BT, H4, HH);
    }
    // 5) layer1 recurrence
    reset_kernel<<<32, 256>>>();
    lstm_kernel<<<128, 512, LSTM_SMEM>>>(Whh1, pXG, pH1);
    // 6) output GEMM: logits = H1 @ Wout^T + bout
    {
        int n4a = (BT * HH) / 4;
        int n4w = (int)(((size_t)CC * HH) / 4);
        split_kernel<<<(n4a + 255) / 256, 256>>>(pH1, pAhi, pAlo, n4a);
        split_kernel<<<(n4w + 255) / 256, 256>>>(Wout, pWhi, pWlo, n4w);
        mma_gemm<<<dim3(BT / 128, CC / 128), 256, GSMEM>>>(
            pAhi, pAlo, pWhi, pWlo, bout, nullptr, out, BT, CC, HH);
    }
}

// round 6
// speedup vs baseline: 2.9236x; 1.2385x over previous
#include <cuda_runtime.h>
#include <cuda_bf16.h>
#include <math.h>
#include <stdint.h>

typedef unsigned long long u64;

#define BT 4096     // B*T rows
#define TT 512
#define BB 8
#define EE 512
#define HH 1024
#define H4 4096
#define CC 32000

// ---------------- scratch (device globals; no allocation allowed) ----------
__device__ float g_XG[(size_t)BT * H4];        // gate pre-acts   64 MB
__device__ float g_H0[(size_t)BT * HH];        // layer0 hidden   16 MB
__device__ float g_H1[(size_t)BT * HH];        // layer1 hidden   16 MB
__device__ __align__(16) __nv_bfloat16 g_hh[2][BB * HH];  // h hi, double buf
__device__ __align__(16) __nv_bfloat16 g_hl[2][BB * HH];  // h lo, double buf
__device__ unsigned g_barcnt;                  // grid barrier counter
__device__ __align__(16) __nv_bfloat16 g_Whi[(size_t)CC * HH];  // 64 MB
__device__ __align__(16) __nv_bfloat16 g_Wlo[(size_t)CC * HH];  // 64 MB
__device__ __align__(16) __nv_bfloat16 g_Ahi[(size_t)BT * HH];  //  8 MB
__device__ __align__(16) __nv_bfloat16 g_Alo[(size_t)BT * HH];  //  8 MB

// ---------------- small helpers ---------------------------------------------
__device__ __forceinline__ uint32_t smem_u32(const void* p) {
    uint32_t a;
    asm("{ .reg .u64 t; cvta.to.shared.u64 t, %1; cvt.u32.u64 %0, t; }"
        : "=r"(a) : "l"(p));
    return a;
}
// pack two consecutive-memory elements (e0 low half, e1 high half)
__device__ __forceinline__ uint32_t packbf(float e0, float e1) {
    uint32_t r;
    asm("cvt.rn.bf16x2.f32 %0, %1, %2;" : "=r"(r) : "f"(e1), "f"(e0));
    return r;
}
__device__ __forceinline__ void cpa16(uint32_t s, const void* g) {
    asm volatile("cp.async.cg.shared.global [%0], [%1], 16;" :: "r"(s), "l"(g));
}
#define CPA_COMMIT() asm volatile("cp.async.commit_group;" ::: "memory")
#define CPA_WAIT1()  asm volatile("cp.async.wait_group 1;"  ::: "memory")
#define CPA_WAIT0()  asm volatile("cp.async.wait_group 0;"  ::: "memory")

#define LDSM4(r, a) \
    asm volatile("ldmatrix.sync.aligned.m8n8.x4.shared.b16 {%0,%1,%2,%3}, [%4];" \
        : "=r"((r)[0]), "=r"((r)[1]), "=r"((r)[2]), "=r"((r)[3]) : "r"(a))

__device__ __forceinline__ void mma_bf(float* d, const uint32_t* a, const uint32_t* b) {
    asm volatile(
        "mma.sync.aligned.m16n8k16.row.col.f32.bf16.bf16.f32 "
        "{%0,%1,%2,%3}, {%4,%5,%6,%7}, {%8,%9}, {%0,%1,%2,%3};"
        : "+f"(d[0]), "+f"(d[1]), "+f"(d[2]), "+f"(d[3])
        : "r"(a[0]), "r"(a[1]), "r"(a[2]), "r"(a[3]), "r"(b[0]), "r"(b[1]));
}

// ---------------- hi/lo bf16 split kernels ----------------------------------
__global__ void split_kernel(const float* __restrict__ src,
                             __nv_bfloat16* __restrict__ hi,
                             __nv_bfloat16* __restrict__ lo, int n4) {
    int i = blockIdx.x * 256 + threadIdx.x;
    if (i >= n4) return;
    float4 v = __ldg((const float4*)src + i);
    float hx = __bfloat162float(__float2bfloat16(v.x));
    float hy = __bfloat162float(__float2bfloat16(v.y));
    float hz = __bfloat162float(__float2bfloat16(v.z));
    float hw = __bfloat162float(__float2bfloat16(v.w));
    uint2 H, L;
    H.x = packbf(hx, hy);         H.y = packbf(hz, hw);
    L.x = packbf(v.x - hx, v.y - hy);
    L.y = packbf(v.z - hz, v.w - hw);
    ((uint2*)hi)[i] = H;
    ((uint2*)lo)[i] = L;
}

// embedding gather -> split bf16 directly into A arrays (K = EE)
__global__ void embed_kernel(const int* __restrict__ x, const float* __restrict__ emb) {
    int row = blockIdx.x;
    int id = __ldg(&x[row]);
    int i = threadIdx.x;                  // 128 threads = EE/4 float4s
    float4 v = __ldg((const float4*)(emb + (size_t)id * EE) + i);
    float hx = __bfloat162float(__float2bfloat16(v.x));
    float hy = __bfloat162float(__float2bfloat16(v.y));
    float hz = __bfloat162float(__float2bfloat16(v.z));
    float hw = __bfloat162float(__float2bfloat16(v.w));
    uint2 H, L;
    H.x = packbf(hx, hy);         H.y = packbf(hz, hw);
    L.x = packbf(v.x - hx, v.y - hy);
    L.y = packbf(v.z - hz, v.w - hw);
    size_t idx = (size_t)row * (EE / 4) + i;
    ((uint2*)g_Ahi)[idx] = H;
    ((uint2*)g_Alo)[idx] = L;
}

// ---------------- bf16 split-MMA GEMM (unchanged from R5) -------------------
#define RS 40                   // smem row stride in bf16 (80 bytes)
#define SSZ (128 * RS * 2)      // 10240 B: one array, one stage
#define GSMEM (8 * SSZ)         // 4 arrays x 2 stages = 81920 B

__device__ __forceinline__ void ld_stage(uint32_t sb, int s,
    const __nv_bfloat16* __restrict__ Ah, const __nv_bfloat16* __restrict__ Al,
    const __nv_bfloat16* __restrict__ Wh, const __nv_bfloat16* __restrict__ Wl,
    int m0, int n0, int K, int k0, int tid)
{
    const int r  = tid >> 2;
    const int kb = (tid & 3) << 3;
    const uint32_t so = sb + (uint32_t)s * SSZ + r * 80 + (kb << 1);
    const size_t gA = (size_t)(m0 + r) * K + k0 + kb;
    const size_t gW = (size_t)(n0 + r) * K + k0 + kb;
    const size_t g64 = (size_t)64 * K;
    cpa16(so,                  Ah + gA);
    cpa16(so + 64 * 80,        Ah + gA + g64);
    cpa16(so + 2 * SSZ,            Al + gA);
    cpa16(so + 2 * SSZ + 64 * 80,  Al + gA + g64);
    cpa16(so + 4 * SSZ,            Wh + gW);
    cpa16(so + 4 * SSZ + 64 * 80,  Wh + gW + g64);
    cpa16(so + 6 * SSZ,            Wl + gW);
    cpa16(so + 6 * SSZ + 64 * 80,  Wl + gW + g64);
}

__device__ __forceinline__ void comp_stage(uint32_t sb, int s, int lane,
                                           int wm, int wn, float (*d)[4][4])
{
    const uint32_t base = sb + (uint32_t)s * SSZ;
    const uint32_t aoff = (lane & 15) * 80 + ((lane >> 4) << 4);
    const uint32_t boff = ((((lane >> 4) << 3) + (lane & 7)) * 80) + (((lane >> 3) & 1) << 4);
#pragma unroll
    for (int ks = 0; ks < 2; ks++) {
        const uint32_t kb = ks << 5;
        uint32_t ah[4][4], al[4][4], bh[2][4], bl[2][4];
#pragma unroll
        for (int mt = 0; mt < 4; mt++) {
            uint32_t a = base + (wm + mt * 16) * 80 + aoff + kb;
            LDSM4(ah[mt], a);
            LDSM4(al[mt], a + 2 * SSZ);
        }
#pragma unroll
        for (int g = 0; g < 2; g++) {
            uint32_t a = base + 4 * SSZ + (wn + g * 16) * 80 + boff + kb;
            LDSM4(bh[g], a);
            LDSM4(bl[g], a + 2 * SSZ);
        }
#pragma unroll
        for (int mt = 0; mt < 4; mt++)
#pragma unroll
            for (int nt = 0; nt < 4; nt++) {
                const uint32_t* ph = &bh[nt >> 1][(nt & 1) << 1];
                const uint32_t* pl = &bl[nt >> 1][(nt & 1) << 1];
                mma_bf(d[mt][nt], ah[mt], ph);
                mma_bf(d[mt][nt], ah[mt], pl);
                mma_bf(d[mt][nt], al[mt], ph);
            }
    }
}

__global__ void __launch_bounds__(256) mma_gemm(
    const __nv_bfloat16* __restrict__ Ahi, const __nv_bfloat16* __restrict__ Alo,
    const __nv_bfloat16* __restrict__ Whi, const __nv_bfloat16* __restrict__ Wlo,
    const float* __restrict__ b1, const float* __restrict__ b2,
    float* __restrict__ C, int M, int N, int K)
{
    extern __shared__ char sm[];
    const uint32_t sb = smem_u32(sm);
    const int tid = threadIdx.x, lane = tid & 31, wid = tid >> 5;
    const int m0 = blockIdx.x << 7, n0 = blockIdx.y << 7;
    const int wm = (wid >> 2) << 6, wn = (wid & 3) << 5;

    float d[4][4][4];
#pragma unroll
    for (int i = 0; i < 4; i++)
#pragma unroll
        for (int j = 0; j < 4; j++)
#pragma unroll
            for (int k = 0; k < 4; k++) d[i][j][k] = 0.f;

    const int KT = K >> 5;
    ld_stage(sb, 0, Ahi, Alo, Whi, Wlo, m0, n0, K, 0, tid);
    CPA_COMMIT();
    for (int kt = 0; kt < KT; kt++) {
        if (kt + 1 < KT) {
            ld_stage(sb, (kt + 1) & 1, Ahi, Alo, Whi, Wlo, m0, n0, K, (kt + 1) << 5, tid);
            CPA_COMMIT();
            CPA_WAIT1();
        } else {
            CPA_WAIT0();
        }
        __syncthreads();
        comp_stage(sb, kt & 1, lane, wm, wn, d);
        __syncthreads();
    }

#pragma unroll
    for (int mt = 0; mt < 4; mt++) {
        const int row0 = m0 + wm + mt * 16 + (lane >> 2);
#pragma unroll
        for (int nt = 0; nt < 4; nt++) {
            const int col = n0 + wn + nt * 8 + ((lane & 3) << 1);
            float bb0 = __ldg(&b1[col]);
            float bb1 = __ldg(&b1[col + 1]);
            if (b2) { bb0 += __ldg(&b2[col]); bb1 += __ldg(&b2[col + 1]); }
            float2 v0 = { d[mt][nt][0] + bb0, d[mt][nt][1] + bb1 };
            float2 v1 = { d[mt][nt][2] + bb0, d[mt][nt][3] + bb1 };
            *(float2*)&C[(size_t)row0 * N + col]       = v0;
            *(float2*)&C[(size_t)(row0 + 8) * N + col] = v1;
        }
    }
}

// ---------------- LSTM recurrence: persistent tensor-core kernel -----------
// 128 blocks x 512 threads (1/SM, co-resident; custom grid barrier). Block
// owns 8 hidden units = 32 gate-rows. Warp w owns k-chunk [w*64, w*64+64).
// Whh held as bf16 hi/lo B-fragments in registers (64 regs/thread).
// Per step: h gathered as bf16 hi/lo into smem; A-frag rows 0-7 = h_hi,
// rows 8-15 = h_lo, so 2 MMAs (vs Wh, Wl) give the FULL 4-product split:
// gate = D_low + D_high = (Ah+Al)(Wh+Wl). fp32 c/h state; h re-split to
// bf16 hi/lo each step (exact to ~17 mantissa bits).
#define HS_STRIDE_B 2064          // bytes per h row (1032 bf16; banks shift 4)
#define PS_STRIDE_W 272           // floats per warp partial row
#define LSTM_SMEM (16 * HS_STRIDE_B + 16 * PS_STRIDE_W * 4)   // 50432 B

__device__ __forceinline__ float sigmoidf_(float x) { return 1.f / (1.f + expf(-x)); }

__global__ void __launch_bounds__(512, 1) lstm_kernel(
    const float* __restrict__ Whh,   // [4096, 1024]
    const float* __restrict__ XG,    // [(b*T+t), 4096] input pre-acts + biases
    float* __restrict__ Hout)        // [(b*T+t), 1024]
{
    extern __shared__ char dsm[];
    char*  hsb = dsm;                          // [16 rows][2064 B] bf16 h hi/lo
    float* ps  = (float*)(dsm + 16 * HS_STRIDE_B);  // [16 warps][272]
    __shared__ float gates[32][8];
    __shared__ float c_s[64];

    const int tid  = threadIdx.x;
    const int blk  = blockIdx.x;
    const int lane = tid & 31;
    const int w    = tid >> 5;        // warp = k-chunk 0..15
    const int kb   = w << 6;          // k base

    // ---- load Whh fragments (hi/lo bf16) into registers, once -------------
    uint32_t bh0[4][4], bh1[4][4], bl0[4][4], bl1[4][4];
#pragma unroll
    for (int nt = 0; nt < 4; nt++) {
        const float* wrow = Whh + (size_t)((nt << 10) + (blk << 3) + (lane >> 2)) * HH
                          + kb + ((lane & 3) << 1);
#pragma unroll
        for (int ks = 0; ks < 4; ks++) {
            float2 v0 = *(const float2*)(wrow + ks * 16);
            float2 v8 = *(const float2*)(wrow + ks * 16 + 8);
            float h0 = __bfloat162float(__float2bfloat16(v0.x));
            float h1 = __bfloat162float(__float2bfloat16(v0.y));
            float h8 = __bfloat162float(__float2bfloat16(v8.x));
            float h9 = __bfloat162float(__float2bfloat16(v8.y));
            bh0[nt][ks] = packbf(h0, h1);
            bh1[nt][ks] = packbf(h8, h9);
            bl0[nt][ks] = packbf(v0.x - h0, v0.y - h1);
            bl1[nt][ks] = packbf(v8.x - h8, v8.y - h9);
        }
    }
    if (tid < 64) c_s[tid] = 0.f;

    // A-frag base addresses (hi row = batch, lo row = batch + 8)
    const char* arow_hi = hsb + (lane >> 2) * HS_STRIDE_B + (kb << 1) + ((lane & 3) << 2);
    const char* arow_lo = arow_hi + 8 * HS_STRIDE_B;
    // partial-store base: ps[w][batch*34 + nt*8 + 2*(lane&3)]
    float* psw = ps + w * PS_STRIDE_W + (lane >> 2) * 34 + ((lane & 3) << 1);

    // reducer mapping (tid < 256): batch = tid>>5, n = tid&31
    const int rb = tid >> 5, rn = tid & 31;
    const float* psr = ps + rb * 34 + rn;
    const int grow_red = ((rn >> 3) << 10) + (blk << 3) + (rn & 7);

    unsigned target = 0;
    for (int t = 0; t < TT; t++) {
        const int cur = t & 1;
        // prefetch gate input (DRAM latency hides under gather+mma)
        float gin = 0.f;
        if (tid < 256)
            gin = __ldg(&XG[(size_t)((rb << 9) + t) * H4 + grow_red]);
        // gather h hi/lo (written by all SMs last step) into smem
        {
            const uint4* shi = (const uint4*)g_hh[cur];
            const uint4* slo = (const uint4*)g_hl[cur];
#pragma unroll
            for (int i = tid; i < 1024; i += 512) {
                int row = i >> 7, c = (i & 127) << 4;
                *(uint4*)(hsb + row * HS_STRIDE_B + c)       = __ldcg(&shi[i]);
                *(uint4*)(hsb + (row + 8) * HS_STRIDE_B + c) = __ldcg(&slo[i]);
            }
        }
        __syncthreads();

        // ---- tensor-core dot: 16 LDS + 32 MMA per warp ---------------------
        float d[4][4];
#pragma unroll
        for (int nt = 0; nt < 4; nt++)
#pragma unroll
            for (int j = 0; j < 4; j++) d[nt][j] = 0.f;
#pragma unroll
        for (int ks = 0; ks < 4; ks++) {
            uint32_t a[4];
            a[0] = *(const uint32_t*)(arow_hi + ks * 32);
            a[1] = *(const uint32_t*)(arow_lo + ks * 32);
            a[2] = *(const uint32_t*)(arow_hi + ks * 32 + 16);
            a[3] = *(const uint32_t*)(arow_lo + ks * 32 + 16);
#pragma unroll
            for (int nt = 0; nt < 4; nt++) {
                uint32_t Bh[2] = { bh0[nt][ks], bh1[nt][ks] };
                uint32_t Bl[2] = { bl0[nt][ks], bl1[nt][ks] };
                mma_bf(d[nt], a, Bh);
                mma_bf(d[nt], a, Bl);
            }
        }
#pragma unroll
        for (int nt = 0; nt < 4; nt++) {
            float2 v = { d[nt][0] + d[nt][2], d[nt][1] + d[nt][3] };
            *(float2*)(psw + nt * 8) = v;
        }
        __syncthreads();

        if (tid < 256) {   // combine 16 warp partials + nonlinearity
            float s = gin;
#pragma unroll
            for (int k2 = 0; k2 < 16; k2++)
                s += psr[k2 * PS_STRIDE_W];
            gates[rn][rb] = ((rn >> 3) == 2) ? tanhf(s) : sigmoidf_(s);
        }
        __syncthreads();

        if (tid < 64) {    // cell update: unit uu, batch bu
            int uu = tid >> 3, bu = tid & 7;
            float c = gates[8 + uu][bu] * c_s[tid] + gates[uu][bu] * gates[16 + uu][bu];
            c_s[tid] = c;
            float h = gates[24 + uu][bu] * tanhf(c);
            int j = (blk << 3) + uu;
            __nv_bfloat16 hh = __float2bfloat16(h);
            g_hh[cur ^ 1][bu * HH + j] = hh;
            g_hl[cur ^ 1][bu * HH + j] = __float2bfloat16(h - __bfloat162float(hh));
            Hout[(size_t)((bu << 9) + t) * HH + j] = h;
            __threadfence();
        }

        if (t != TT - 1) {      // grid barrier (counter zeroed by reset_kernel)
            target += 128;
            __syncthreads();
            if (tid == 0) {
                atomicAdd(&g_barcnt, 1u);
                while (*(volatile unsigned*)&g_barcnt < target) { }
                __threadfence();
            }
            __syncthreads();
        }
    }
}

__global__ void reset_kernel() {
    unsigned t = blockIdx.x * blockDim.x + threadIdx.x;   // 8192 threads
    if (t == 0) g_barcnt = 0u;
    if (t < (BB * HH) / 2) {
        ((uint32_t*)g_hh[0])[t] = 0u;
        ((uint32_t*)g_hl[0])[t] = 0u;
    }
}

// ---------------- launch ----------------------------------------------------
extern "C" void kernel_launch(void* const* d_in, const int* in_sizes, int n_in,
                              void* d_out, int out_size)
{
    const int*   x    = (const int*)  d_in[0];
    const float* emb  = (const float*)d_in[1];
    const float* Wih0 = (const float*)d_in[2];
    const float* Whh0 = (const float*)d_in[3];
    const float* bih0 = (const float*)d_in[4];
    const float* bhh0 = (const float*)d_in[5];
    const float* Wih1 = (const float*)d_in[6];
    const float* Whh1 = (const float*)d_in[7];
    const float* bih1 = (const float*)d_in[8];
    const float* bhh1 = (const float*)d_in[9];
    const float* Wout = (const float*)d_in[10];
    const float* bout = (const float*)d_in[11];
    float* out = (float*)d_out;

    float *pXG, *pH0, *pH1;
    __nv_bfloat16 *pWhi, *pWlo, *pAhi, *pAlo;
    cudaGetSymbolAddress((void**)&pXG, g_XG);
    cudaGetSymbolAddress((void**)&pH0, g_H0);
    cudaGetSymbolAddress((void**)&pH1, g_H1);
    cudaGetSymbolAddress((void**)&pWhi, g_Whi);
    cudaGetSymbolAddress((void**)&pWlo, g_Wlo);
    cudaGetSymbolAddress((void**)&pAhi, g_Ahi);
    cudaGetSymbolAddress((void**)&pAlo, g_Alo);

    cudaFuncSetAttribute(lstm_kernel,
                         cudaFuncAttributeMaxDynamicSharedMemorySize, LSTM_SMEM);
    cudaFuncSetAttribute(mma_gemm,
                         cudaFuncAttributeMaxDynamicSharedMemorySize, GSMEM);

    // 1) embedding (writes split bf16 X0 into Ahi/Alo)
    embed_kernel<<<BT, 128>>>(x, emb);
    // 2) layer0 input GEMM: XG = X0 @ Wih0^T + bih0 + bhh0
    {
        int n4 = (H4 * EE) / 4;
        split_kernel<<<(n4 + 255) / 256, 256>>>(Wih0, pWhi, pWlo, n4);
        mma_gemm<<<dim3(BT / 128, H4 / 128), 256, GSMEM>>>(
            pAhi, pAlo, pWhi, pWlo, bih0, bhh0, pXG, BT, H4, EE);
    }
    // 3) layer0 recurrence
    reset_kernel<<<32, 256>>>();
    lstm_kernel<<<128, 512, LSTM_SMEM>>>(Whh0, pXG, pH0);
    // 4) layer1 input GEMM: XG = H0 @ Wih1^T + bih1 + bhh1
    {
        int n4a = (BT * HH) / 4, n4w = (H4 * HH) / 4;
        split_kernel<<<(n4a + 255) / 256, 256>>>(pH0, pAhi, pAlo, n4a);
        split_kernel<<<(n4w + 255) / 256, 256>>>(Wih1, pWhi, pWlo, n4w);
        mma_gemm<<<dim3(BT / 128, H4 / 128), 256, GSMEM>>>(
            pAhi, pAlo, pWhi, pWlo, bih1, bhh1, pXG, BT, H4, HH);
    }
    // 5) layer1 recurrence
    reset_kernel<<<32, 256>>>();
    lstm_kernel<<<128, 512, LSTM_SMEM>>>(Whh1, pXG, pH1);
    // 6) output GEMM: logits = H1 @ Wout^T + bout
    {
        int n4a = (BT * HH) / 4;
        int n4w = (int)(((size_t)CC * HH) / 4);
        split_kernel<<<(n4a + 255) / 256, 256>>>(pH1, pAhi, pAlo, n4a);
        split_kernel<<<(n4w + 255) / 256, 256>>>(Wout, pWhi, pWlo, n4w);
        mma_gemm<<<dim3(BT / 128, CC / 128), 256, GSMEM>>>(
            pAhi, pAlo, pWhi, pWlo, bout, nullptr, out, BT, CC, HH);
    }
}